// round 2
// baseline (speedup 1.0000x reference)
#include <cuda_runtime.h>
#include <cstdint>

#define S_LEN   16384
#define HID     1280
#define NH      16
#define HD      80
#define WIN     64
#define NW      256
#define N_QKV   3840

// Scratch (allocation-free rule: __device__ globals)
__device__ float g_qkv[(size_t)S_LEN * N_QKV];   // [S, 3*HID], RoPE applied in-place to q,k
__device__ float g_att[(size_t)S_LEN * HID];     // attention output [S, HID]

__device__ __forceinline__ float to_tf32(float x) {
    uint32_t u;
    asm("cvt.rna.tf32.f32 %0, %1;" : "=r"(u) : "f"(x));
    return __uint_as_float(u);
}

__device__ __forceinline__ void mma_tf32(float* c, const uint32_t* a, const uint32_t* b) {
    asm volatile(
        "mma.sync.aligned.m16n8k8.row.col.f32.tf32.tf32.f32 "
        "{%0,%1,%2,%3}, {%4,%5,%6,%7}, {%8,%9}, {%0,%1,%2,%3};"
        : "+f"(c[0]), "+f"(c[1]), "+f"(c[2]), "+f"(c[3])
        : "r"(a[0]), "r"(a[1]), "r"(a[2]), "r"(a[3]),
          "r"(b[0]), "r"(b[1]));
}

// ---------------------------------------------------------------------------
// TF32 GEMM: C[M,N] = A[M,K] @ B[K,N] + bias[N]
// BM=128 BN=128 BK=16, 256 threads (8 warps, 2x4 layout, 64x32 warp tiles).
// MODE selects scratch wiring at compile time (no host symbol lookups):
//   MODE 0: A = arg,    C = g_qkv   (QKV GEMM)
//   MODE 1: A = g_att,  C = arg     (proj GEMM)
// ---------------------------------------------------------------------------
template <int MODE>
__global__ __launch_bounds__(256)
void gemm_tf32(const float* __restrict__ Aarg, const float* __restrict__ B,
               const float* __restrict__ bias, float* __restrict__ Carg,
               int M, int N, int K)
{
    const float* __restrict__ A = (MODE == 0) ? Aarg : (const float*)g_att;
    float* __restrict__ C       = (MODE == 0) ? (float*)g_qkv : Carg;

    __shared__ float As[2][128 * 20];
    __shared__ float Bs[2][16 * 136];

    const int tid  = threadIdx.x;
    const int lane = tid & 31;
    const int warp = tid >> 5;
    const int wm = warp & 1;      // 0..1 -> M offset *64
    const int wn = warp >> 1;     // 0..3 -> N offset *32
    const int gr = lane >> 2;     // group row 0..7
    const int tg = lane & 3;      // thread-in-group 0..3
    const int bm = blockIdx.y * 128;
    const int bn = blockIdx.x * 128;

    // global-load assignments (2 float4 each for A and B per thread)
    int aRow[2], aCol[2], bRow[2], bCol[2];
#pragma unroll
    for (int i = 0; i < 2; i++) {
        int f = tid + i * 256;
        aRow[i] = f >> 2;          aCol[i] = (f & 3) * 4;    // A tile 128 x 16
        bRow[i] = f >> 5;          bCol[i] = (f & 31) * 4;   // B tile 16 x 128
    }

    float acc[4][4][4];
#pragma unroll
    for (int mi = 0; mi < 4; mi++)
#pragma unroll
        for (int ni = 0; ni < 4; ni++)
#pragma unroll
            for (int r = 0; r < 4; r++) acc[mi][ni][r] = 0.0f;

    float4 aReg[2], bReg[2];

    const int KT = K / 16;

    // prologue: load tile 0
#pragma unroll
    for (int i = 0; i < 2; i++) {
        aReg[i] = *(const float4*)(A + (size_t)(bm + aRow[i]) * K + aCol[i]);
        bReg[i] = *(const float4*)(B + (size_t)bRow[i] * N + bn + bCol[i]);
    }
#pragma unroll
    for (int i = 0; i < 2; i++) {
        float4 t;
        t.x = to_tf32(aReg[i].x); t.y = to_tf32(aReg[i].y);
        t.z = to_tf32(aReg[i].z); t.w = to_tf32(aReg[i].w);
        *(float4*)(&As[0][aRow[i] * 20 + aCol[i]]) = t;
        t.x = to_tf32(bReg[i].x); t.y = to_tf32(bReg[i].y);
        t.z = to_tf32(bReg[i].z); t.w = to_tf32(bReg[i].w);
        *(float4*)(&Bs[0][bRow[i] * 136 + bCol[i]]) = t;
    }
    __syncthreads();

    for (int kt = 0; kt < KT; kt++) {
        const int buf = kt & 1;
        if (kt + 1 < KT) {
#pragma unroll
            for (int i = 0; i < 2; i++) {
                aReg[i] = *(const float4*)(A + (size_t)(bm + aRow[i]) * K + (kt + 1) * 16 + aCol[i]);
                bReg[i] = *(const float4*)(B + (size_t)((kt + 1) * 16 + bRow[i]) * N + bn + bCol[i]);
            }
        }

#pragma unroll
        for (int ks = 0; ks < 2; ks++) {
            uint32_t a[4][4], b[4][2];
#pragma unroll
            for (int mi = 0; mi < 4; mi++) {
                const int r = wm * 64 + mi * 16 + gr;
                const float* ap = &As[buf][r * 20 + ks * 8];
                a[mi][0] = __float_as_uint(ap[tg]);
                a[mi][1] = __float_as_uint(ap[8 * 20 + tg]);
                a[mi][2] = __float_as_uint(ap[tg + 4]);
                a[mi][3] = __float_as_uint(ap[8 * 20 + tg + 4]);
            }
#pragma unroll
            for (int ni = 0; ni < 4; ni++) {
                const int cix = wn * 32 + ni * 8 + gr;
                const float* bp = &Bs[buf][(ks * 8) * 136 + cix];
                b[ni][0] = __float_as_uint(bp[tg * 136]);
                b[ni][1] = __float_as_uint(bp[(tg + 4) * 136]);
            }
#pragma unroll
            for (int mi = 0; mi < 4; mi++)
#pragma unroll
                for (int ni = 0; ni < 4; ni++)
                    mma_tf32(acc[mi][ni], a[mi], b[ni]);
        }

        if (kt + 1 < KT) {
            __syncthreads();
            const int nbuf = (kt + 1) & 1;
#pragma unroll
            for (int i = 0; i < 2; i++) {
                float4 t;
                t.x = to_tf32(aReg[i].x); t.y = to_tf32(aReg[i].y);
                t.z = to_tf32(aReg[i].z); t.w = to_tf32(aReg[i].w);
                *(float4*)(&As[nbuf][aRow[i] * 20 + aCol[i]]) = t;
                t.x = to_tf32(bReg[i].x); t.y = to_tf32(bReg[i].y);
                t.z = to_tf32(bReg[i].z); t.w = to_tf32(bReg[i].w);
                *(float4*)(&Bs[nbuf][bRow[i] * 136 + bCol[i]]) = t;
            }
            __syncthreads();
        }
    }

    // epilogue: bias + store (float2 per row pair)
#pragma unroll
    for (int mi = 0; mi < 4; mi++) {
        const int r = bm + wm * 64 + mi * 16 + gr;
#pragma unroll
        for (int ni = 0; ni < 4; ni++) {
            const int c = bn + wn * 32 + ni * 8 + tg * 2;
            const float2 bv = *(const float2*)(bias + c);
            float2 o0, o1;
            o0.x = acc[mi][ni][0] + bv.x; o0.y = acc[mi][ni][1] + bv.y;
            o1.x = acc[mi][ni][2] + bv.x; o1.y = acc[mi][ni][3] + bv.y;
            *(float2*)(C + (size_t)r * N + c)        = o0;
            *(float2*)(C + (size_t)(r + 8) * N + c)  = o1;
        }
    }
}

// ---------------------------------------------------------------------------
// RoPE in-place on q,k sections of g_qkv.
// q'[d]    = q[d]*cos[d]    - q[d+40]*sin[d]
// q'[d+40] = q[d+40]*cos[d+40] + q[d]*sin[d+40]
// One thread per (s, h, d<40) pair; handles q and k.
// ---------------------------------------------------------------------------
__global__ void rope_kernel(const float* __restrict__ cosb, const float* __restrict__ sinb)
{
    const int idx = blockIdx.x * blockDim.x + threadIdx.x;   // < S*NH*40
    const int d = idx % 40;
    const int t = idx / 40;
    const int h = t % NH;
    const int s = t / NH;

    const float c0 = cosb[s * HD + d];
    const float c1 = cosb[s * HD + d + 40];
    const float s0 = sinb[s * HD + d];
    const float s1 = sinb[s * HD + d + 40];

    const size_t base = (size_t)s * N_QKV + h * HD + d;

    float q0 = g_qkv[base], q1 = g_qkv[base + 40];
    g_qkv[base]      = q0 * c0 - q1 * s0;
    g_qkv[base + 40] = q1 * c1 + q0 * s1;

    float k0 = g_qkv[base + HID], k1 = g_qkv[base + HID + 40];
    g_qkv[base + HID]      = k0 * c0 - k1 * s0;
    g_qkv[base + HID + 40] = k1 * c1 + k0 * s1;
}

// ---------------------------------------------------------------------------
// Windowed attention: one block per (window, head). 64x64 scores over hd=80.
// 256 threads / 8 warps, each warp owns 8 q-rows.
// Dynamic smem: Qs[64*80] (reused as P[64*64]), Ks[64*84] (padded), Vs[64*80].
// ---------------------------------------------------------------------------
#define ATT_SMEM ((WIN * HD + WIN * 84 + WIN * HD) * 4)

__global__ __launch_bounds__(256)
void attn_kernel()
{
    extern __shared__ float sm[];
    float* Qs = sm;                    // 64*80 (later reused as P 64*64)
    float* Ks = sm + WIN * HD;         // 64*84
    float* Vs = Ks + WIN * 84;         // 64*80

    const int w = blockIdx.x;
    const int h = blockIdx.y;
    const int tid = threadIdx.x;
    const int warp = tid >> 5;
    const int lane = tid & 31;

    const float* qbase = g_qkv + (size_t)w * WIN * N_QKV + h * HD;

    // Load Q,K,V tiles (64 rows x 80 = 20 float4 per row)
    for (int f = tid; f < WIN * 20; f += 256) {
        const int r  = f / 20;
        const int dq = (f % 20) * 4;
        const float* rp = qbase + (size_t)r * N_QKV + dq;
        *(float4*)(Qs + r * HD + dq) = *(const float4*)(rp);
        *(float4*)(Ks + r * 84 + dq) = *(const float4*)(rp + HID);
        *(float4*)(Vs + r * HD + dq) = *(const float4*)(rp + 2 * HID);
    }
    __syncthreads();

    const int r0 = warp * 8;
    const int c0 = lane, c1 = lane + 32;

    // scores: acc[i][j] = q[r0+i] . k[c_j]
    float acc[8][2];
#pragma unroll
    for (int i = 0; i < 8; i++) { acc[i][0] = 0.f; acc[i][1] = 0.f; }

    for (int d = 0; d < HD; d += 4) {
        const float4 k0 = *(const float4*)(Ks + c0 * 84 + d);
        const float4 k1 = *(const float4*)(Ks + c1 * 84 + d);
#pragma unroll
        for (int i = 0; i < 8; i++) {
            const float4 q = *(const float4*)(Qs + (r0 + i) * HD + d);
            acc[i][0] += q.x * k0.x + q.y * k0.y + q.z * k0.z + q.w * k0.w;
            acc[i][1] += q.x * k1.x + q.y * k1.y + q.z * k1.z + q.w * k1.w;
        }
    }

    // softmax per row (cols split 2-per-lane across warp)
    const float scale = 0.111803398874989485f;  // 80^-0.5
    float pr[8][2];
#pragma unroll
    for (int i = 0; i < 8; i++) {
        float s0 = acc[i][0] * scale;
        float s1 = acc[i][1] * scale;
        float m = fmaxf(s0, s1);
#pragma unroll
        for (int off = 16; off > 0; off >>= 1)
            m = fmaxf(m, __shfl_xor_sync(0xffffffffu, m, off));
        float e0 = __expf(s0 - m);
        float e1 = __expf(s1 - m);
        float sum = e0 + e1;
#pragma unroll
        for (int off = 16; off > 0; off >>= 1)
            sum += __shfl_xor_sync(0xffffffffu, sum, off);
        const float inv = 1.0f / sum;
        pr[i][0] = e0 * inv;
        pr[i][1] = e1 * inv;
    }

    __syncthreads();           // all warps done reading Qs -> safe to reuse as P
    float* Ps = Qs;            // 64 x 64
#pragma unroll
    for (int i = 0; i < 8; i++) {
        Ps[(r0 + i) * WIN + c0] = pr[i][0];
        Ps[(r0 + i) * WIN + c1] = pr[i][1];
    }
    __syncthreads();

    // AV: out[r][d] = sum_c P[r][c] * V[c][d]; lanes cover d = lane, lane+32, lane+64
    const int d0 = lane, d1 = lane + 32, d2 = lane + 64;
    const bool has2 = (lane < 16);
    float o0[8], o1[8], o2[8];
#pragma unroll
    for (int i = 0; i < 8; i++) { o0[i] = 0.f; o1[i] = 0.f; o2[i] = 0.f; }

    for (int c = 0; c < WIN; c += 4) {
        float v0[4], v1[4], v2[4];
#pragma unroll
        for (int j = 0; j < 4; j++) {
            v0[j] = Vs[(c + j) * HD + d0];
            v1[j] = Vs[(c + j) * HD + d1];
            v2[j] = has2 ? Vs[(c + j) * HD + d2] : 0.f;
        }
#pragma unroll
        for (int i = 0; i < 8; i++) {
            const float4 p = *(const float4*)(Ps + (r0 + i) * WIN + c);
            o0[i] += p.x * v0[0] + p.y * v0[1] + p.z * v0[2] + p.w * v0[3];
            o1[i] += p.x * v1[0] + p.y * v1[1] + p.z * v1[2] + p.w * v1[3];
            o2[i] += p.x * v2[0] + p.y * v2[1] + p.z * v2[2] + p.w * v2[3];
        }
    }

#pragma unroll
    for (int i = 0; i < 8; i++) {
        const size_t base = (size_t)(w * WIN + r0 + i) * HID + h * HD;
        g_att[base + d0] = o0[i];
        g_att[base + d1] = o1[i];
        if (has2) g_att[base + d2] = o2[i];
    }
}

// ---------------------------------------------------------------------------
// kernel_launch: GEMM(qkv) -> RoPE -> attention -> GEMM(proj)
// ---------------------------------------------------------------------------
extern "C" void kernel_launch(void* const* d_in, const int* in_sizes, int n_in,
                              void* d_out, int out_size)
{
    const float* x      = (const float*)d_in[0];
    const float* cosb   = (const float*)d_in[1];
    const float* sinb   = (const float*)d_in[2];
    // d_in[3] = cu_seqlens (uniform 64-windows; structure hardcoded)
    const float* w_qkv  = (const float*)d_in[4];
    const float* b_qkv  = (const float*)d_in[5];
    const float* w_proj = (const float*)d_in[6];
    const float* b_proj = (const float*)d_in[7];
    float* out = (float*)d_out;

    cudaFuncSetAttribute(attn_kernel, cudaFuncAttributeMaxDynamicSharedMemorySize, ATT_SMEM);

    // 1) QKV GEMM: [S, HID] @ [HID, 3HID] + bias -> g_qkv
    gemm_tf32<0><<<dim3(N_QKV / 128, S_LEN / 128), 256>>>(
        x, w_qkv, b_qkv, nullptr, S_LEN, N_QKV, HID);

    // 2) RoPE on q,k
    rope_kernel<<<(S_LEN * NH * 40) / 256, 256>>>(cosb, sinb);

    // 3) windowed attention -> g_att
    attn_kernel<<<dim3(NW, NH), 256, ATT_SMEM>>>();

    // 4) output projection: g_att @ w_proj + b_proj -> out
    gemm_tf32<1><<<dim3(HID / 128, S_LEN / 128), 256>>>(
        nullptr, w_proj, b_proj, out, S_LEN, HID, HID);
}

// round 4
// speedup vs baseline: 1.0001x; 1.0001x over previous
#include <cuda_runtime.h>
#include <cstdint>

#define S_LEN   16384
#define HID     1280
#define NH      16
#define HD      80
#define WIN     64
#define NW      256
#define N_QKV   3840

// Scratch (allocation-free rule: __device__ globals)
__device__ float g_qkv[(size_t)S_LEN * N_QKV];   // [S, 3*HID], RoPE applied in-place to q,k
__device__ float g_att[(size_t)S_LEN * HID];     // attention output [S, HID]

__device__ __forceinline__ float to_tf32(float x) {
    uint32_t u;
    asm("cvt.rna.tf32.f32 %0, %1;" : "=r"(u) : "f"(x));
    return __uint_as_float(u);
}

__device__ __forceinline__ void mma_tf32(float* c, const uint32_t* a, const uint32_t* b) {
    asm volatile(
        "mma.sync.aligned.m16n8k8.row.col.f32.tf32.tf32.f32 "
        "{%0,%1,%2,%3}, {%4,%5,%6,%7}, {%8,%9}, {%0,%1,%2,%3};"
        : "+f"(c[0]), "+f"(c[1]), "+f"(c[2]), "+f"(c[3])
        : "r"(a[0]), "r"(a[1]), "r"(a[2]), "r"(a[3]),
          "r"(b[0]), "r"(b[1]));
}

// ---------------------------------------------------------------------------
// TF32 GEMM: C[M,N] = A[M,K] @ B[K,N] + bias[N]
// BM=128 BN=128 BK=16, 256 threads (8 warps, 2x4 layout, 64x32 warp tiles).
// MODE selects scratch wiring at compile time (no host symbol lookups):
//   MODE 0: A = arg,    C = g_qkv   (QKV GEMM)
//   MODE 1: A = g_att,  C = arg     (proj GEMM)
// ---------------------------------------------------------------------------
template <int MODE>
__global__ __launch_bounds__(256)
void gemm_tf32(const float* __restrict__ Aarg, const float* __restrict__ B,
               const float* __restrict__ bias, float* __restrict__ Carg,
               int M, int N, int K)
{
    const float* __restrict__ A = (MODE == 0) ? Aarg : (const float*)g_att;
    float* __restrict__ C       = (MODE == 0) ? (float*)g_qkv : Carg;

    __shared__ float As[2][128 * 20];
    __shared__ float Bs[2][16 * 136];

    const int tid  = threadIdx.x;
    const int lane = tid & 31;
    const int warp = tid >> 5;
    const int wm = warp & 1;      // 0..1 -> M offset *64
    const int wn = warp >> 1;     // 0..3 -> N offset *32
    const int gr = lane >> 2;     // group row 0..7
    const int tg = lane & 3;      // thread-in-group 0..3
    const int bm = blockIdx.y * 128;
    const int bn = blockIdx.x * 128;

    // global-load assignments (2 float4 each for A and B per thread)
    int aRow[2], aCol[2], bRow[2], bCol[2];
#pragma unroll
    for (int i = 0; i < 2; i++) {
        int f = tid + i * 256;
        aRow[i] = f >> 2;          aCol[i] = (f & 3) * 4;    // A tile 128 x 16
        bRow[i] = f >> 5;          bCol[i] = (f & 31) * 4;   // B tile 16 x 128
    }

    float acc[4][4][4];
#pragma unroll
    for (int mi = 0; mi < 4; mi++)
#pragma unroll
        for (int ni = 0; ni < 4; ni++)
#pragma unroll
            for (int r = 0; r < 4; r++) acc[mi][ni][r] = 0.0f;

    float4 aReg[2], bReg[2];

    const int KT = K / 16;

    // prologue: load tile 0
#pragma unroll
    for (int i = 0; i < 2; i++) {
        aReg[i] = *(const float4*)(A + (size_t)(bm + aRow[i]) * K + aCol[i]);
        bReg[i] = *(const float4*)(B + (size_t)bRow[i] * N + bn + bCol[i]);
    }
#pragma unroll
    for (int i = 0; i < 2; i++) {
        float4 t;
        t.x = to_tf32(aReg[i].x); t.y = to_tf32(aReg[i].y);
        t.z = to_tf32(aReg[i].z); t.w = to_tf32(aReg[i].w);
        *(float4*)(&As[0][aRow[i] * 20 + aCol[i]]) = t;
        t.x = to_tf32(bReg[i].x); t.y = to_tf32(bReg[i].y);
        t.z = to_tf32(bReg[i].z); t.w = to_tf32(bReg[i].w);
        *(float4*)(&Bs[0][bRow[i] * 136 + bCol[i]]) = t;
    }
    __syncthreads();

    for (int kt = 0; kt < KT; kt++) {
        const int buf = kt & 1;
        if (kt + 1 < KT) {
#pragma unroll
            for (int i = 0; i < 2; i++) {
                aReg[i] = *(const float4*)(A + (size_t)(bm + aRow[i]) * K + (kt + 1) * 16 + aCol[i]);
                bReg[i] = *(const float4*)(B + (size_t)((kt + 1) * 16 + bRow[i]) * N + bn + bCol[i]);
            }
        }

#pragma unroll
        for (int ks = 0; ks < 2; ks++) {
            uint32_t a[4][4], b[4][2];
#pragma unroll
            for (int mi = 0; mi < 4; mi++) {
                const int r = wm * 64 + mi * 16 + gr;
                const float* ap = &As[buf][r * 20 + ks * 8];
                a[mi][0] = __float_as_uint(ap[tg]);
                a[mi][1] = __float_as_uint(ap[8 * 20 + tg]);
                a[mi][2] = __float_as_uint(ap[tg + 4]);
                a[mi][3] = __float_as_uint(ap[8 * 20 + tg + 4]);
            }
#pragma unroll
            for (int ni = 0; ni < 4; ni++) {
                const int cix = wn * 32 + ni * 8 + gr;
                const float* bp = &Bs[buf][(ks * 8) * 136 + cix];
                b[ni][0] = __float_as_uint(bp[tg * 136]);
                b[ni][1] = __float_as_uint(bp[(tg + 4) * 136]);
            }
#pragma unroll
            for (int mi = 0; mi < 4; mi++)
#pragma unroll
                for (int ni = 0; ni < 4; ni++)
                    mma_tf32(acc[mi][ni], a[mi], b[ni]);
        }

        if (kt + 1 < KT) {
            __syncthreads();
            const int nbuf = (kt + 1) & 1;
#pragma unroll
            for (int i = 0; i < 2; i++) {
                float4 t;
                t.x = to_tf32(aReg[i].x); t.y = to_tf32(aReg[i].y);
                t.z = to_tf32(aReg[i].z); t.w = to_tf32(aReg[i].w);
                *(float4*)(&As[nbuf][aRow[i] * 20 + aCol[i]]) = t;
                t.x = to_tf32(bReg[i].x); t.y = to_tf32(bReg[i].y);
                t.z = to_tf32(bReg[i].z); t.w = to_tf32(bReg[i].w);
                *(float4*)(&Bs[nbuf][bRow[i] * 136 + bCol[i]]) = t;
            }
            __syncthreads();
        }
    }

    // epilogue: bias + store (float2 per row pair)
#pragma unroll
    for (int mi = 0; mi < 4; mi++) {
        const int r = bm + wm * 64 + mi * 16 + gr;
#pragma unroll
        for (int ni = 0; ni < 4; ni++) {
            const int c = bn + wn * 32 + ni * 8 + tg * 2;
            const float2 bv = *(const float2*)(bias + c);
            float2 o0, o1;
            o0.x = acc[mi][ni][0] + bv.x; o0.y = acc[mi][ni][1] + bv.y;
            o1.x = acc[mi][ni][2] + bv.x; o1.y = acc[mi][ni][3] + bv.y;
            *(float2*)(C + (size_t)r * N + c)        = o0;
            *(float2*)(C + (size_t)(r + 8) * N + c)  = o1;
        }
    }
}

// ---------------------------------------------------------------------------
// RoPE in-place on q,k sections of g_qkv.
// q'[d]    = q[d]*cos[d]    - q[d+40]*sin[d]
// q'[d+40] = q[d+40]*cos[d+40] + q[d]*sin[d+40]
// One thread per (s, h, d<40) pair; handles q and k.
// ---------------------------------------------------------------------------
__global__ void rope_kernel(const float* __restrict__ cosb, const float* __restrict__ sinb)
{
    const int idx = blockIdx.x * blockDim.x + threadIdx.x;   // < S*NH*40
    const int d = idx % 40;
    const int t = idx / 40;
    const int h = t % NH;
    const int s = t / NH;

    const float c0 = cosb[s * HD + d];
    const float c1 = cosb[s * HD + d + 40];
    const float s0 = sinb[s * HD + d];
    const float s1 = sinb[s * HD + d + 40];

    const size_t base = (size_t)s * N_QKV + h * HD + d;

    float q0 = g_qkv[base], q1 = g_qkv[base + 40];
    g_qkv[base]      = q0 * c0 - q1 * s0;
    g_qkv[base + 40] = q1 * c1 + q0 * s1;

    float k0 = g_qkv[base + HID], k1 = g_qkv[base + HID + 40];
    g_qkv[base + HID]      = k0 * c0 - k1 * s0;
    g_qkv[base + HID + 40] = k1 * c1 + k0 * s1;
}

// ---------------------------------------------------------------------------
// Windowed attention: one block per (window, head). 64x64 scores over hd=80.
// 256 threads / 8 warps, each warp owns 8 q-rows.
// Dynamic smem: Qs[64*80] (reused as P[64*64]), Ks[64*84] (padded), Vs[64*80].
// ---------------------------------------------------------------------------
#define ATT_SMEM ((WIN * HD + WIN * 84 + WIN * HD) * 4)

__global__ __launch_bounds__(256)
void attn_kernel()
{
    extern __shared__ float sm[];
    float* Qs = sm;                    // 64*80 (later reused as P 64*64)
    float* Ks = sm + WIN * HD;         // 64*84
    float* Vs = Ks + WIN * 84;         // 64*80

    const int w = blockIdx.x;
    const int h = blockIdx.y;
    const int tid = threadIdx.x;
    const int warp = tid >> 5;
    const int lane = tid & 31;

    const float* qbase = g_qkv + (size_t)w * WIN * N_QKV + h * HD;

    // Load Q,K,V tiles (64 rows x 80 = 20 float4 per row)
    for (int f = tid; f < WIN * 20; f += 256) {
        const int r  = f / 20;
        const int dq = (f % 20) * 4;
        const float* rp = qbase + (size_t)r * N_QKV + dq;
        *(float4*)(Qs + r * HD + dq) = *(const float4*)(rp);
        *(float4*)(Ks + r * 84 + dq) = *(const float4*)(rp + HID);
        *(float4*)(Vs + r * HD + dq) = *(const float4*)(rp + 2 * HID);
    }
    __syncthreads();

    const int r0 = warp * 8;
    const int c0 = lane, c1 = lane + 32;

    // scores: acc[i][j] = q[r0+i] . k[c_j]
    float acc[8][2];
#pragma unroll
    for (int i = 0; i < 8; i++) { acc[i][0] = 0.f; acc[i][1] = 0.f; }

    for (int d = 0; d < HD; d += 4) {
        const float4 k0 = *(const float4*)(Ks + c0 * 84 + d);
        const float4 k1 = *(const float4*)(Ks + c1 * 84 + d);
#pragma unroll
        for (int i = 0; i < 8; i++) {
            const float4 q = *(const float4*)(Qs + (r0 + i) * HD + d);
            acc[i][0] += q.x * k0.x + q.y * k0.y + q.z * k0.z + q.w * k0.w;
            acc[i][1] += q.x * k1.x + q.y * k1.y + q.z * k1.z + q.w * k1.w;
        }
    }

    // softmax per row (cols split 2-per-lane across warp)
    const float scale = 0.111803398874989485f;  // 80^-0.5
    float pr[8][2];
#pragma unroll
    for (int i = 0; i < 8; i++) {
        float s0 = acc[i][0] * scale;
        float s1 = acc[i][1] * scale;
        float m = fmaxf(s0, s1);
#pragma unroll
        for (int off = 16; off > 0; off >>= 1)
            m = fmaxf(m, __shfl_xor_sync(0xffffffffu, m, off));
        float e0 = __expf(s0 - m);
        float e1 = __expf(s1 - m);
        float sum = e0 + e1;
#pragma unroll
        for (int off = 16; off > 0; off >>= 1)
            sum += __shfl_xor_sync(0xffffffffu, sum, off);
        const float inv = 1.0f / sum;
        pr[i][0] = e0 * inv;
        pr[i][1] = e1 * inv;
    }

    __syncthreads();           // all warps done reading Qs -> safe to reuse as P
    float* Ps = Qs;            // 64 x 64
#pragma unroll
    for (int i = 0; i < 8; i++) {
        Ps[(r0 + i) * WIN + c0] = pr[i][0];
        Ps[(r0 + i) * WIN + c1] = pr[i][1];
    }
    __syncthreads();

    // AV: out[r][d] = sum_c P[r][c] * V[c][d]; lanes cover d = lane, lane+32, lane+64
    const int d0 = lane, d1 = lane + 32, d2 = lane + 64;
    const bool has2 = (lane < 16);
    float o0[8], o1[8], o2[8];
#pragma unroll
    for (int i = 0; i < 8; i++) { o0[i] = 0.f; o1[i] = 0.f; o2[i] = 0.f; }

    for (int c = 0; c < WIN; c += 4) {
        float v0[4], v1[4], v2[4];
#pragma unroll
        for (int j = 0; j < 4; j++) {
            v0[j] = Vs[(c + j) * HD + d0];
            v1[j] = Vs[(c + j) * HD + d1];
            v2[j] = has2 ? Vs[(c + j) * HD + d2] : 0.f;
        }
#pragma unroll
        for (int i = 0; i < 8; i++) {
            const float4 p = *(const float4*)(Ps + (r0 + i) * WIN + c);
            o0[i] += p.x * v0[0] + p.y * v0[1] + p.z * v0[2] + p.w * v0[3];
            o1[i] += p.x * v1[0] + p.y * v1[1] + p.z * v1[2] + p.w * v1[3];
            o2[i] += p.x * v2[0] + p.y * v2[1] + p.z * v2[2] + p.w * v2[3];
        }
    }

#pragma unroll
    for (int i = 0; i < 8; i++) {
        const size_t base = (size_t)(w * WIN + r0 + i) * HID + h * HD;
        g_att[base + d0] = o0[i];
        g_att[base + d1] = o1[i];
        if (has2) g_att[base + d2] = o2[i];
    }
}

// ---------------------------------------------------------------------------
// kernel_launch: GEMM(qkv) -> RoPE -> attention -> GEMM(proj)
// ---------------------------------------------------------------------------
extern "C" void kernel_launch(void* const* d_in, const int* in_sizes, int n_in,
                              void* d_out, int out_size)
{
    const float* x      = (const float*)d_in[0];
    const float* cosb   = (const float*)d_in[1];
    const float* sinb   = (const float*)d_in[2];
    // d_in[3] = cu_seqlens (uniform 64-windows; structure hardcoded)
    const float* w_qkv  = (const float*)d_in[4];
    const float* b_qkv  = (const float*)d_in[5];
    const float* w_proj = (const float*)d_in[6];
    const float* b_proj = (const float*)d_in[7];
    float* out = (float*)d_out;

    cudaFuncSetAttribute(attn_kernel, cudaFuncAttributeMaxDynamicSharedMemorySize, ATT_SMEM);

    // 1) QKV GEMM: [S, HID] @ [HID, 3HID] + bias -> g_qkv
    gemm_tf32<0><<<dim3(N_QKV / 128, S_LEN / 128), 256>>>(
        x, w_qkv, b_qkv, nullptr, S_LEN, N_QKV, HID);

    // 2) RoPE on q,k
    rope_kernel<<<(S_LEN * NH * 40) / 256, 256>>>(cosb, sinb);

    // 3) windowed attention -> g_att
    attn_kernel<<<dim3(NW, NH), 256, ATT_SMEM>>>();

    // 4) output projection: g_att @ w_proj + b_proj -> out
    gemm_tf32<1><<<dim3(HID / 128, S_LEN / 128), 256>>>(
        nullptr, w_proj, b_proj, out, S_LEN, HID, HID);
}